// round 16
// baseline (speedup 1.0000x reference)
#include <cuda_runtime.h>

// ---------------------------------------------------------------------------
// Hypernet: two tiny LSTMs generate a (32,16,7,7) conv weight; then a 7x7
// pad-3 fp32 conv over (64,16,224,224) -> (64,32,224,224).
//
// lstm_kernel: 512 thr / 16 warps; warp w owns h-indices 8w..8w+7 across ALL
//   FOUR gate quadrants (tile0=[i|f], tile1=[g|o] rows), so gates/c/h are
//   computed fully in-warp -> ONE syncthreads per step while keeping 16
//   warps of HMMA throughput. h + reduction buffers double-buffered.
// conv_mma_kernel: R12 inner loop; 28-row y-bands (grid (2,8,64) = 1024
//   slots ~ 7/SM over all 148 SMs); 14-slot ring (10 read + 4 staged,
//   exactly disjoint).
// ---------------------------------------------------------------------------

typedef unsigned long long ull;
typedef unsigned int u32;

__device__ float g_wflat[25088];   // t = oc*784 + ci*49 + ky*7 + kx

__device__ __forceinline__ float sigmf(float x){ return 1.0f / (1.0f + __expf(-x)); }

__device__ __forceinline__ u32 f2h2(float f0, float f1){
    u32 r;
    asm("{ .reg .b16 l, h; cvt.rn.f16.f32 l, %1; cvt.rn.f16.f32 h, %2; mov.b32 %0, {l, h}; }" : "=r"(r) : "f"(f0), "f"(f1));
    return r;
}
__device__ __forceinline__ void ldm4(u32* r, u32 addr){
    asm volatile("ldmatrix.sync.aligned.m8n8.x4.shared.b16 {%0,%1,%2,%3}, [%4];" : "=r"(r[0]), "=r"(r[1]), "=r"(r[2]), "=r"(r[3]) : "r"(addr));
}
__device__ __forceinline__ void mma16816(float* d, const u32* a, u32 b0, u32 b1){
    asm volatile("mma.sync.aligned.m16n8k16.row.col.f32.f16.f16.f32 {%0,%1,%2,%3}, {%4,%5,%6,%7}, {%8,%9}, {%0,%1,%2,%3};" : "+f"(d[0]), "+f"(d[1]), "+f"(d[2]), "+f"(d[3]) : "r"(a[0]), "r"(a[1]), "r"(a[2]), "r"(a[3]), "r"(b0), "r"(b1));
}

// ---------------------------------------------------------------------------
// LSTM kernel: 1 block x 512 threads (16 warps), one sync per step.
// ---------------------------------------------------------------------------
__global__ void __launch_bounds__(512, 1) lstm_kernel(
    const float* __restrict__ p,
    const float* __restrict__ Wih1, const float* __restrict__ Whh1,
    const float* __restrict__ bih1, const float* __restrict__ bhh1,
    const float* __restrict__ Wih2, const float* __restrict__ Whh2,
    const float* __restrict__ bih2, const float* __restrict__ bhh2,
    const float* __restrict__ fc1)
{
    __shared__ u32   hbuf[2][64];    // h as fp16x2 pairs, double-buffered
    __shared__ float red[2][16];
    __shared__ float p_sh[128];
    __shared__ float fc_sh[128];
    __shared__ float seq[128];

    const int t    = threadIdx.x;
    const int lane = t & 31;
    const int w    = t >> 5;          // 0..15
    const int q    = lane >> 2;       // 0..7
    const int c0   = (lane & 3) * 2;  // 0,2,4,6
    const int j    = 8 * w + q;       // this thread's h index (x4 redundant)

    if (t < 128){ p_sh[t] = p[t]; fc_sh[t] = fc1[t]; }
    if (t < 64){ hbuf[0][t] = 0u; hbuf[1][t] = 0u; }

    u32 Wf[16][4];                    // [k] tile0 (i|f), [8+k] tile1 (g|o)
    float wi[4], bb[4];

    {
        const float* W = Whh1;
        const int ri = j, rf = 128 + j, rg = 256 + j, ro = 384 + j;
        #pragma unroll
        for (int k = 0; k < 8; k++){
            const int base = 16 * k + c0;
            u32* f0 = Wf[k];
            f0[0] = f2h2(W[ri * 128 + base],     W[ri * 128 + base + 1]);
            f0[1] = f2h2(W[rf * 128 + base],     W[rf * 128 + base + 1]);
            f0[2] = f2h2(W[ri * 128 + base + 8], W[ri * 128 + base + 9]);
            f0[3] = f2h2(W[rf * 128 + base + 8], W[rf * 128 + base + 9]);
            u32* f1 = Wf[8 + k];
            f1[0] = f2h2(W[rg * 128 + base],     W[rg * 128 + base + 1]);
            f1[1] = f2h2(W[ro * 128 + base],     W[ro * 128 + base + 1]);
            f1[2] = f2h2(W[rg * 128 + base + 8], W[rg * 128 + base + 9]);
            f1[3] = f2h2(W[ro * 128 + base + 8], W[ro * 128 + base + 9]);
        }
        wi[0] = Wih1[ri]; wi[1] = Wih1[rf]; wi[2] = Wih1[rg]; wi[3] = Wih1[ro];
        bb[0] = bih1[ri] + bhh1[ri]; bb[1] = bih1[rf] + bhh1[rf];
        bb[2] = bih1[rg] + bhh1[rg]; bb[3] = bih1[ro] + bhh1[ro];
    }
    float c_cell = 0.0f;
    int pb = 0;
    __syncthreads();

    for (int phase = 0; phase < 4; phase++){
        if (phase == 2){
            __syncthreads();
            const float* W = Whh2;
            const int ri = j, rf = 128 + j, rg = 256 + j, ro = 384 + j;
            #pragma unroll
            for (int k = 0; k < 8; k++){
                const int base = 16 * k + c0;
                u32* f0 = Wf[k];
                f0[0] = f2h2(W[ri * 128 + base],     W[ri * 128 + base + 1]);
                f0[1] = f2h2(W[rf * 128 + base],     W[rf * 128 + base + 1]);
                f0[2] = f2h2(W[ri * 128 + base + 8], W[ri * 128 + base + 9]);
                f0[3] = f2h2(W[rf * 128 + base + 8], W[rf * 128 + base + 9]);
                u32* f1 = Wf[8 + k];
                f1[0] = f2h2(W[rg * 128 + base],     W[rg * 128 + base + 1]);
                f1[1] = f2h2(W[ro * 128 + base],     W[ro * 128 + base + 1]);
                f1[2] = f2h2(W[rg * 128 + base + 8], W[rg * 128 + base + 9]);
                f1[3] = f2h2(W[ro * 128 + base + 8], W[ro * 128 + base + 9]);
            }
            wi[0] = Wih2[ri]; wi[1] = Wih2[rf]; wi[2] = Wih2[rg]; wi[3] = Wih2[ro];
            bb[0] = bih2[ri] + bhh2[ri]; bb[1] = bih2[rf] + bhh2[rf];
            bb[2] = bih2[rg] + bhh2[rg]; bb[3] = bih2[ro] + bhh2[ro];
            c_cell = 0.0f;
            if (t < 64){ hbuf[0][t] = 0u; hbuf[1][t] = 0u; }
            __syncthreads();
        }
        const int  steps   = (phase == 3) ? 160 : 128;
        const bool collect = (phase & 1);
        for (int tt = 0; tt < steps; tt++){
            const u32* hb = hbuf[pb];
            float d0[4] = {0.f, 0.f, 0.f, 0.f};
            float d1[4] = {0.f, 0.f, 0.f, 0.f};
            #pragma unroll
            for (int k = 0; k < 8; k++){
                const u32 b0 = hb[8 * k + (lane & 3)];
                const u32 b1 = hb[8 * k + 4 + (lane & 3)];
                mma16816(d0, Wf[k],     b0, b1);
                mma16816(d1, Wf[8 + k], b0, b1);
            }
            const float x = (phase == 2) ? seq[tt] : p_sh[tt & 127];
            const float gi = d0[0] + fmaf(wi[0], x, bb[0]);
            const float gf = d0[2] + fmaf(wi[1], x, bb[1]);
            const float gg = d1[0] + fmaf(wi[2], x, bb[2]);
            const float go = d1[2] + fmaf(wi[3], x, bb[3]);
            c_cell = sigmf(gf) * c_cell + sigmf(gi) * tanhf(gg);
            const float h = sigmf(go) * tanhf(c_cell);

            // h of neighbor j^1 lives at lane^4
            const float hn = __shfl_xor_sync(0xffffffffu, h, 4);
            if ((lane & 7) == 0){     // q even, col 0
                hbuf[pb ^ 1][4 * w + (q >> 1)] = f2h2(h, hn);
            }
            if (collect){
                float pr = ((lane & 3) == 0) ? (h * fc_sh[j]) : 0.0f;
                #pragma unroll
                for (int o = 16; o >= 4; o >>= 1)
                    pr += __shfl_down_sync(0xffffffffu, pr, o);
                if (lane == 0) red[pb][w] = pr;
            }
            __syncthreads();
            if (collect && t == 0){
                float s = 0.0f;
                #pragma unroll
                for (int i = 0; i < 16; i++) s += red[pb][i];
                if (phase == 1) seq[tt]     = s;
                else            g_wflat[tt] = s;
            }
            pb ^= 1;
        }
    }
    __syncthreads();
    // replicate the converged 128-period (computed steps 32..159 are source)
    for (int i = 160 + t; i < 25088; i += 512)
        g_wflat[i] = g_wflat[32 + ((i - 32) & 127)];
}

// ---------------------------------------------------------------------------
// mma.sync conv: R12 inner loop, 28-row y-bands, 14-slot ring.
// A ring: 14 y-slots x 120 x-positions x 32B (16 ci fp16). slot(y)=(y+3)%14.
// B: 49 taps x 32 oc x 32B. Block 224 thr = 7 warps x 16 px; grid (2,8,64).
// ---------------------------------------------------------------------------
#define A_SLOT_B  3840
#define B_OFF     53760
#define CONV_SMEM 103936

__device__ __forceinline__ void stage_row(const float* __restrict__ in,
                                          unsigned char* cvsm,
                                          int n, int x0, int ymax, int yp, int tid)
{
    if (yp > ymax) return;
    const int slot = (yp + 3) % 14;
    for (int idx = tid; idx < 236; idx += 224){
        const int kg = idx / 118;
        const int pp = idx - kg * 118;
        const int xg = x0 - 3 + pp;
        const bool ok = ((unsigned)yp < 224u) && ((unsigned)xg < 224u);
        u32 hh[4];
        #pragma unroll
        for (int jj = 0; jj < 4; jj++){
            float f0 = 0.0f, f1 = 0.0f;
            if (ok){
                const float* bp = in + (((size_t)(n * 16 + kg * 8 + 2 * jj)) * 224 + yp) * 224 + xg;
                f0 = bp[0];
                f1 = bp[50176];
            }
            hh[jj] = f2h2(f0, f1);
        }
        const int aoff = slot * A_SLOT_B + pp * 32 + kg * 16;
        uint4 hv; hv.x = hh[0]; hv.y = hh[1]; hv.z = hh[2]; hv.w = hh[3];
        *(uint4*)(cvsm + aoff) = hv;
    }
}

__global__ void __launch_bounds__(224, 2) conv_mma_kernel(
    const float* __restrict__ in, float* __restrict__ out)
{
    extern __shared__ __align__(1024) unsigned char cvsm[];
    const int tid  = threadIdx.x;
    const int warp = tid >> 5;
    const int lane = tid & 31;
    const int x0   = blockIdx.x * 112;
    const int y0   = blockIdx.y * 28;
    const int ymax = y0 + 30;
    const int n    = blockIdx.z;
    const u32 smb  = (u32)__cvta_generic_to_shared(cvsm);

    for (int i = tid; i < 12544; i += 224){
        const int tap = i / 256;
        const int rem = i - tap * 256;
        const int oc  = rem >> 3;
        const int c2  = (rem & 7) * 2;
        const int wb  = oc * 784 + c2 * 49 + tap;
        const u32 pairv = f2h2(g_wflat[wb], g_wflat[wb + 49]);
        *(u32*)(cvsm + B_OFF + tap * 1024 + oc * 32 + c2 * 2) = pairv;
    }

    const u32 lxo = (u32)((lane & 15) * 32 + (lane >> 4) * 16);
    const int wx  = warp * 16;

    for (int yp = y0 - 3; yp <= y0 + 6; yp++){
        stage_row(in, cvsm, n, x0, ymax, yp, tid);
    }
    __syncthreads();

    for (int r = y0; r < y0 + 28; r += 4){
        float d[64];
        #pragma unroll
        for (int i = 0; i < 64; i++) d[i] = 0.0f;

        #pragma unroll 1
        for (int ky = 0; ky < 7; ky++){
            u32 ab[4];
            #pragma unroll
            for (int row = 0; row < 4; row++){
                const int slot = (r + row + ky) % 14;
                ab[row] = smb + (u32)(slot * A_SLOT_B + wx * 32) + lxo;
            }
            #pragma unroll 1
            for (int kx = 0; kx < 7; kx++){
                const u32 wb = smb + (u32)(B_OFF + (ky * 7 + kx) * 1024) + lxo;
                u32 b01[4], b23[4];
                ldm4(b01, wb);
                ldm4(b23, wb + 512);
                #pragma unroll
                for (int row = 0; row < 4; row++){
                    u32 af[4];
                    ldm4(af, ab[row] + (u32)(kx * 32));
                    float* dr = d + row * 16;
                    mma16816(dr + 0,  af, b01[0], b01[2]);
                    mma16816(dr + 4,  af, b01[1], b01[3]);
                    mma16816(dr + 8,  af, b23[0], b23[2]);
                    mma16816(dr + 12, af, b23[1], b23[3]);
                }
            }
        }

        const int px = wx + (lane >> 2);
        #pragma unroll
        for (int row = 0; row < 4; row++){
            float* ob = out + ((size_t)(n * 32) * 224 + (r + row)) * 224 + x0;
            const float* dr = d + row * 16;
            #pragma unroll
            for (int g = 0; g < 4; g++){
                const int oc = g * 8 + 2 * (lane & 3);
                ob[(size_t)oc * 50176 + px]           = dr[g * 4 + 0];
                ob[(size_t)(oc + 1) * 50176 + px]     = dr[g * 4 + 1];
                ob[(size_t)oc * 50176 + px + 8]       = dr[g * 4 + 2];
                ob[(size_t)(oc + 1) * 50176 + px + 8] = dr[g * 4 + 3];
            }
        }

        stage_row(in, cvsm, n, x0, ymax, r + 7,  tid);
        stage_row(in, cvsm, n, x0, ymax, r + 8,  tid);
        stage_row(in, cvsm, n, x0, ymax, r + 9,  tid);
        stage_row(in, cvsm, n, x0, ymax, r + 10, tid);
        __syncthreads();
    }
}

// ---------------------------------------------------------------------------
extern "C" void kernel_launch(void* const* d_in, const int* in_sizes, int n_in,
                              void* d_out, int out_size)
{
    const float* p    = (const float*)d_in[0];
    const float* inp  = (const float*)d_in[1];
    const float* Wih1 = (const float*)d_in[2];
    const float* Whh1 = (const float*)d_in[3];
    const float* bih1 = (const float*)d_in[4];
    const float* bhh1 = (const float*)d_in[5];
    const float* Wih2 = (const float*)d_in[6];
    const float* Whh2 = (const float*)d_in[7];
    const float* bih2 = (const float*)d_in[8];
    const float* bhh2 = (const float*)d_in[9];
    const float* fc1  = (const float*)d_in[10];
    float* out = (float*)d_out;

    cudaFuncSetAttribute(conv_mma_kernel,
                         cudaFuncAttributeMaxDynamicSharedMemorySize, CONV_SMEM);

    lstm_kernel<<<1, 512>>>(p, Wih1, Whh1, bih1, bhh1,
                            Wih2, Whh2, bih2, bhh2, fc1);

    dim3 grid(2, 8, 64);
    conv_mma_kernel<<<grid, 224, CONV_SMEM>>>(inp, out);
}

// round 17
// speedup vs baseline: 1.0239x; 1.0239x over previous
#include <cuda_runtime.h>

// ---------------------------------------------------------------------------
// Hypernet: two tiny LSTMs generate a (32,16,7,7) conv weight; then a 7x7
// pad-3 fp32 conv over (64,16,224,224) -> (64,32,224,224).
//
// lstm_kernel: one-sync/16-warp skeleton (R16) + split-k MMA accumulators
//   (halves the HMMA RAW chain) + MUFU-based tanh/sigmoid (halves the gate
//   latency chain). Phase-3: 160 computed steps, remainder periodic.
// conv_mma_kernel: R12 verbatim (proven 624 us).
// ---------------------------------------------------------------------------

typedef unsigned long long ull;
typedef unsigned int u32;

__device__ float g_wflat[25088];   // t = oc*784 + ci*49 + ky*7 + kx

__device__ __forceinline__ float sigmf(float x){ return 1.0f / (1.0f + __expf(-x)); }
__device__ __forceinline__ float tanhfast(float x){ return 1.0f - 2.0f / (1.0f + __expf(2.0f * x)); }

__device__ __forceinline__ u32 f2h2(float f0, float f1){
    u32 r;
    asm("{ .reg .b16 l, h; cvt.rn.f16.f32 l, %1; cvt.rn.f16.f32 h, %2; mov.b32 %0, {l, h}; }" : "=r"(r) : "f"(f0), "f"(f1));
    return r;
}
__device__ __forceinline__ void ldm4(u32* r, u32 addr){
    asm volatile("ldmatrix.sync.aligned.m8n8.x4.shared.b16 {%0,%1,%2,%3}, [%4];" : "=r"(r[0]), "=r"(r[1]), "=r"(r[2]), "=r"(r[3]) : "r"(addr));
}
__device__ __forceinline__ void mma16816(float* d, const u32* a, u32 b0, u32 b1){
    asm volatile("mma.sync.aligned.m16n8k16.row.col.f32.f16.f16.f32 {%0,%1,%2,%3}, {%4,%5,%6,%7}, {%8,%9}, {%0,%1,%2,%3};" : "+f"(d[0]), "+f"(d[1]), "+f"(d[2]), "+f"(d[3]) : "r"(a[0]), "r"(a[1]), "r"(a[2]), "r"(a[3]), "r"(b0), "r"(b1));
}

// ---------------------------------------------------------------------------
// LSTM kernel: 1 block x 512 threads (16 warps), one sync per step.
// Warp w owns h-indices 8w..8w+7 across all four gate quadrants.
// ---------------------------------------------------------------------------
__global__ void __launch_bounds__(512, 1) lstm_kernel(
    const float* __restrict__ p,
    const float* __restrict__ Wih1, const float* __restrict__ Whh1,
    const float* __restrict__ bih1, const float* __restrict__ bhh1,
    const float* __restrict__ Wih2, const float* __restrict__ Whh2,
    const float* __restrict__ bih2, const float* __restrict__ bhh2,
    const float* __restrict__ fc1)
{
    __shared__ u32   hbuf[2][64];    // h as fp16x2 pairs, double-buffered
    __shared__ float red[2][16];
    __shared__ float p_sh[128];
    __shared__ float fc_sh[128];
    __shared__ float seq[128];

    const int t    = threadIdx.x;
    const int lane = t & 31;
    const int w    = t >> 5;          // 0..15
    const int q    = lane >> 2;       // 0..7
    const int c0   = (lane & 3) * 2;  // 0,2,4,6
    const int j    = 8 * w + q;       // this thread's h index (x4 redundant)

    if (t < 128){ p_sh[t] = p[t]; fc_sh[t] = fc1[t]; }
    if (t < 64){ hbuf[0][t] = 0u; hbuf[1][t] = 0u; }

    u32 Wf[16][4];                    // [k] tile0 (i|f), [8+k] tile1 (g|o)
    float wi[4], bb[4];

    {
        const float* W = Whh1;
        const int ri = j, rf = 128 + j, rg = 256 + j, ro = 384 + j;
        #pragma unroll
        for (int k = 0; k < 8; k++){
            const int base = 16 * k + c0;
            u32* f0 = Wf[k];
            f0[0] = f2h2(W[ri * 128 + base],     W[ri * 128 + base + 1]);
            f0[1] = f2h2(W[rf * 128 + base],     W[rf * 128 + base + 1]);
            f0[2] = f2h2(W[ri * 128 + base + 8], W[ri * 128 + base + 9]);
            f0[3] = f2h2(W[rf * 128 + base + 8], W[rf * 128 + base + 9]);
            u32* f1 = Wf[8 + k];
            f1[0] = f2h2(W[rg * 128 + base],     W[rg * 128 + base + 1]);
            f1[1] = f2h2(W[ro * 128 + base],     W[ro * 128 + base + 1]);
            f1[2] = f2h2(W[rg * 128 + base + 8], W[rg * 128 + base + 9]);
            f1[3] = f2h2(W[ro * 128 + base + 8], W[ro * 128 + base + 9]);
        }
        wi[0] = Wih1[ri]; wi[1] = Wih1[rf]; wi[2] = Wih1[rg]; wi[3] = Wih1[ro];
        bb[0] = bih1[ri] + bhh1[ri]; bb[1] = bih1[rf] + bhh1[rf];
        bb[2] = bih1[rg] + bhh1[rg]; bb[3] = bih1[ro] + bhh1[ro];
    }
    float c_cell = 0.0f;
    int pb = 0;
    __syncthreads();

    for (int phase = 0; phase < 4; phase++){
        if (phase == 2){
            __syncthreads();
            const float* W = Whh2;
            const int ri = j, rf = 128 + j, rg = 256 + j, ro = 384 + j;
            #pragma unroll
            for (int k = 0; k < 8; k++){
                const int base = 16 * k + c0;
                u32* f0 = Wf[k];
                f0[0] = f2h2(W[ri * 128 + base],     W[ri * 128 + base + 1]);
                f0[1] = f2h2(W[rf * 128 + base],     W[rf * 128 + base + 1]);
                f0[2] = f2h2(W[ri * 128 + base + 8], W[ri * 128 + base + 9]);
                f0[3] = f2h2(W[rf * 128 + base + 8], W[rf * 128 + base + 9]);
                u32* f1 = Wf[8 + k];
                f1[0] = f2h2(W[rg * 128 + base],     W[rg * 128 + base + 1]);
                f1[1] = f2h2(W[ro * 128 + base],     W[ro * 128 + base + 1]);
                f1[2] = f2h2(W[rg * 128 + base + 8], W[rg * 128 + base + 9]);
                f1[3] = f2h2(W[ro * 128 + base + 8], W[ro * 128 + base + 9]);
            }
            wi[0] = Wih2[ri]; wi[1] = Wih2[rf]; wi[2] = Wih2[rg]; wi[3] = Wih2[ro];
            bb[0] = bih2[ri] + bhh2[ri]; bb[1] = bih2[rf] + bhh2[rf];
            bb[2] = bih2[rg] + bhh2[rg]; bb[3] = bih2[ro] + bhh2[ro];
            c_cell = 0.0f;
            if (t < 64){ hbuf[0][t] = 0u; hbuf[1][t] = 0u; }
            __syncthreads();
        }
        const int  steps   = (phase == 3) ? 160 : 128;
        const bool collect = (phase & 1);
        for (int tt = 0; tt < steps; tt++){
            const u32* hb = hbuf[pb];
            float d0a[4] = {0.f, 0.f, 0.f, 0.f};
            float d1a[4] = {0.f, 0.f, 0.f, 0.f};
            float d0b[4] = {0.f, 0.f, 0.f, 0.f};
            float d1b[4] = {0.f, 0.f, 0.f, 0.f};
            #pragma unroll
            for (int k = 0; k < 4; k++){
                const u32 b0 = hb[8 * k + (lane & 3)];
                const u32 b1 = hb[8 * k + 4 + (lane & 3)];
                mma16816(d0a, Wf[k],     b0, b1);
                mma16816(d1a, Wf[8 + k], b0, b1);
            }
            #pragma unroll
            for (int k = 4; k < 8; k++){
                const u32 b0 = hb[8 * k + (lane & 3)];
                const u32 b1 = hb[8 * k + 4 + (lane & 3)];
                mma16816(d0b, Wf[k],     b0, b1);
                mma16816(d1b, Wf[8 + k], b0, b1);
            }
            const float x = (phase == 2) ? seq[tt] : p_sh[tt & 127];
            const float gi = (d0a[0] + d0b[0]) + fmaf(wi[0], x, bb[0]);
            const float gf = (d0a[2] + d0b[2]) + fmaf(wi[1], x, bb[1]);
            const float gg = (d1a[0] + d1b[0]) + fmaf(wi[2], x, bb[2]);
            const float go = (d1a[2] + d1b[2]) + fmaf(wi[3], x, bb[3]);
            c_cell = sigmf(gf) * c_cell + sigmf(gi) * tanhfast(gg);
            const float h = sigmf(go) * tanhfast(c_cell);

            // h of neighbor j^1 lives at lane^4
            const float hn = __shfl_xor_sync(0xffffffffu, h, 4);
            if ((lane & 7) == 0){     // q even, col 0
                hbuf[pb ^ 1][4 * w + (q >> 1)] = f2h2(h, hn);
            }
            if (collect){
                float pr = ((lane & 3) == 0) ? (h * fc_sh[j]) : 0.0f;
                pr += __shfl_down_sync(0xffffffffu, pr, 16);
                pr += __shfl_down_sync(0xffffffffu, pr, 8);
                pr += __shfl_down_sync(0xffffffffu, pr, 4);
                if (lane == 0) red[pb][w] = pr;
            }
            __syncthreads();
            if (collect && t == 0){
                float s = 0.0f;
                #pragma unroll
                for (int i = 0; i < 16; i++) s += red[pb][i];
                if (phase == 1) seq[tt]     = s;
                else            g_wflat[tt] = s;
            }
            pb ^= 1;
        }
    }
    __syncthreads();
    // replicate the converged 128-period (computed steps 32..159 are source)
    for (int i = 160 + t; i < 25088; i += 512)
        g_wflat[i] = g_wflat[32 + ((i - 32) & 127)];
}

// ---------------------------------------------------------------------------
// mma.sync conv (R12 verbatim, proven 624 us).
// A ring: 12 y-slots x 120 x-positions x 32B (16 ci fp16). slot(y)=(y+3)%12.
// B: 49 taps x 32 oc x 32B. Block 224 thr = 7 warps x 16 px; grid (2,2,64).
// ---------------------------------------------------------------------------
#define A_SLOT_B  3840
#define B_OFF     46080
#define CONV_SMEM 96256

__device__ __forceinline__ void stage_row(const float* __restrict__ in,
                                          unsigned char* cvsm,
                                          int n, int x0, int ymax, int yp, int tid)
{
    if (yp > ymax) return;
    const int slot = (yp + 3) % 12;
    for (int idx = tid; idx < 236; idx += 224){
        const int kg = idx / 118;
        const int pp = idx - kg * 118;
        const int xg = x0 - 3 + pp;
        const bool ok = ((unsigned)yp < 224u) && ((unsigned)xg < 224u);
        u32 hh[4];
        #pragma unroll
        for (int jj = 0; jj < 4; jj++){
            float f0 = 0.0f, f1 = 0.0f;
            if (ok){
                const float* bp = in + (((size_t)(n * 16 + kg * 8 + 2 * jj)) * 224 + yp) * 224 + xg;
                f0 = bp[0];
                f1 = bp[50176];
            }
            hh[jj] = f2h2(f0, f1);
        }
        const int aoff = slot * A_SLOT_B + pp * 32 + kg * 16;
        uint4 hv; hv.x = hh[0]; hv.y = hh[1]; hv.z = hh[2]; hv.w = hh[3];
        *(uint4*)(cvsm + aoff) = hv;
    }
}

__global__ void __launch_bounds__(224, 2) conv_mma_kernel(
    const float* __restrict__ in, float* __restrict__ out)
{
    extern __shared__ __align__(1024) unsigned char cvsm[];
    const int tid  = threadIdx.x;
    const int warp = tid >> 5;
    const int lane = tid & 31;
    const int x0   = blockIdx.x * 112;
    const int y0   = blockIdx.y * 112;
    const int ymax = y0 + 114;
    const int n    = blockIdx.z;
    const u32 smb  = (u32)__cvta_generic_to_shared(cvsm);

    for (int i = tid; i < 12544; i += 224){
        const int tap = i / 256;
        const int rem = i - tap * 256;
        const int oc  = rem >> 3;
        const int c2  = (rem & 7) * 2;
        const int wb  = oc * 784 + c2 * 49 + tap;
        const u32 pairv = f2h2(g_wflat[wb], g_wflat[wb + 49]);
        *(u32*)(cvsm + B_OFF + tap * 1024 + oc * 32 + c2 * 2) = pairv;
    }

    const u32 lxo = (u32)((lane & 15) * 32 + (lane >> 4) * 16);
    const int wx  = warp * 16;

    for (int yp = y0 - 3; yp <= y0 + 6; yp++){
        stage_row(in, cvsm, n, x0, ymax, yp, tid);
    }
    __syncthreads();

    for (int r = y0; r < y0 + 112; r += 4){
        float d[64];
        #pragma unroll
        for (int i = 0; i < 64; i++) d[i] = 0.0f;

        #pragma unroll 1
        for (int ky = 0; ky < 7; ky++){
            u32 ab[4];
            #pragma unroll
            for (int row = 0; row < 4; row++){
                const int slot = (r + row + ky) % 12;
                ab[row] = smb + (u32)(slot * A_SLOT_B + wx * 32) + lxo;
            }
            #pragma unroll 1
            for (int kx = 0; kx < 7; kx++){
                const u32 wb = smb + (u32)(B_OFF + (ky * 7 + kx) * 1024) + lxo;
                u32 b01[4], b23[4];
                ldm4(b01, wb);
                ldm4(b23, wb + 512);
                #pragma unroll
                for (int row = 0; row < 4; row++){
                    u32 af[4];
                    ldm4(af, ab[row] + (u32)(kx * 32));
                    float* dr = d + row * 16;
                    mma16816(dr + 0,  af, b01[0], b01[2]);
                    mma16816(dr + 4,  af, b01[1], b01[3]);
                    mma16816(dr + 8,  af, b23[0], b23[2]);
                    mma16816(dr + 12, af, b23[1], b23[3]);
                }
            }
        }

        const int px = wx + (lane >> 2);
        #pragma unroll
        for (int row = 0; row < 4; row++){
            float* ob = out + ((size_t)(n * 32) * 224 + (r + row)) * 224 + x0;
            const float* dr = d + row * 16;
            #pragma unroll
            for (int g = 0; g < 4; g++){
                const int oc = g * 8 + 2 * (lane & 3);
                ob[(size_t)oc * 50176 + px]           = dr[g * 4 + 0];
                ob[(size_t)(oc + 1) * 50176 + px]     = dr[g * 4 + 1];
                ob[(size_t)oc * 50176 + px + 8]       = dr[g * 4 + 2];
                ob[(size_t)(oc + 1) * 50176 + px + 8] = dr[g * 4 + 3];
            }
        }

        stage_row(in, cvsm, n, x0, ymax, r + 7,  tid);
        stage_row(in, cvsm, n, x0, ymax, r + 8,  tid);
        stage_row(in, cvsm, n, x0, ymax, r + 9,  tid);
        stage_row(in, cvsm, n, x0, ymax, r + 10, tid);
        __syncthreads();
    }
}

// ---------------------------------------------------------------------------
extern "C" void kernel_launch(void* const* d_in, const int* in_sizes, int n_in,
                              void* d_out, int out_size)
{
    const float* p    = (const float*)d_in[0];
    const float* inp  = (const float*)d_in[1];
    const float* Wih1 = (const float*)d_in[2];
    const float* Whh1 = (const float*)d_in[3];
    const float* bih1 = (const float*)d_in[4];
    const float* bhh1 = (const float*)d_in[5];
    const float* Wih2 = (const float*)d_in[6];
    const float* Whh2 = (const float*)d_in[7];
    const float* bih2 = (const float*)d_in[8];
    const float* bhh2 = (const float*)d_in[9];
    const float* fc1  = (const float*)d_in[10];
    float* out = (float*)d_out;

    cudaFuncSetAttribute(conv_mma_kernel,
                         cudaFuncAttributeMaxDynamicSharedMemorySize, CONV_SMEM);

    lstm_kernel<<<1, 512>>>(p, Wih1, Whh1, bih1, bhh1,
                            Wih2, Whh2, bih2, bhh2, fc1);

    dim3 grid(2, 2, 64);
    conv_mma_kernel<<<grid, 224, CONV_SMEM>>>(inp, out);
}